// round 1
// baseline (speedup 1.0000x reference)
#include <cuda_runtime.h>

#define NB 8
#define NN 64
#define NT 50
#define TO 49      // output timesteps (t = NT-1 is never needed)
#define ND 4
#define NH 64
#define EPN 63     // edges per recv node

// Scratch (static __device__ — no allocation in kernel_launch)
__device__ float g_u[NB * TO * NN * NH];   // u' = W1r @ x + b1   (per node)
__device__ float g_v[NB * TO * NN * NH];   // v  = W1s @ x        (per node)
__device__ float g_w2t[NH * NH];           // fc2_w[1] transposed: [k][j]

// ---------------------------------------------------------------------------
// Kernel 0: transpose fc2_w[1] into g_w2t so kernel 2 smem load is coalesced
// and conflict-free on both sides.
__global__ void k_prep(const float* __restrict__ fc2_w) {
    int idx = blockIdx.x * blockDim.x + threadIdx.x;   // 0..4095
    if (idx >= NH * NH) return;
    int j = idx >> 6;
    int k = idx & 63;
    g_w2t[k * NH + j] = fc2_w[NH * NH + j * NH + k];   // fc2_w[1][j][k]
}

// ---------------------------------------------------------------------------
// Kernel 1: per-node fc1 factorization.
// u'[b,t,n,h] = b1[h] + sum_d W1[h][d]   * x[b,t,n,d]
// v [b,t,n,h] =         sum_d W1[h][4+d] * x[b,t,n,d]
__global__ void k_node_embed(const float* __restrict__ inputs,
                             const float* __restrict__ fc1_w,
                             const float* __restrict__ fc1_b) {
    int gid = blockIdx.x * blockDim.x + threadIdx.x;
    if (gid >= NB * TO * NN * NH) return;
    int h    = gid & 63;
    int node = gid >> 6;              // ((b*49 + t)*64 + n)
    int n    = node & 63;
    int bt   = node >> 6;
    int t    = bt % TO;
    int b    = bt / TO;

    // x_in[b,t,n,d] = inputs[b,n,t,d]
    const float* x = inputs + (((size_t)b * NN + n) * NT + t) * ND;
    const float* w = fc1_w + NH * 2 * ND + h * 2 * ND;   // fc1_w[1][h][:]
    float u = fc1_b[NH + h];                              // fc1_b[1][h]
    float v = 0.f;
#pragma unroll
    for (int d = 0; d < ND; d++) {
        u += w[d] * x[d];
        v += w[ND + d] * x[d];
    }
    g_u[gid] = u;
    g_v[gid] = v;
}

// ---------------------------------------------------------------------------
// Kernel 2: fused edge MLP (fc2) + aggregation + node MLP + output.
// One block per (b, t, recv-node n). 256 threads = 8 warps.
// Each warp handles 2 edge-slots per iteration, 4 iterations -> 64 slots
// (slot 63 is a dummy masked by rt=0; 63 real edges).
__global__ void __launch_bounds__(256)
k_edge(const float* __restrict__ inputs,
       const float* __restrict__ rel_type,
       const float* __restrict__ fc2_b,
       const float* __restrict__ out1_w, const float* __restrict__ out1_b,
       const float* __restrict__ out2_w, const float* __restrict__ out2_b,
       const float* __restrict__ out3_w, const float* __restrict__ out3_b,
       float* __restrict__ out) {
    __shared__ float w2t_s[NH * NH];      // [k][j]
    __shared__ float u_s[NH];             // u' of the recv node
    __shared__ float rt_s[64];            // rel_type[b,0,n*63+s,1], slot 63 -> 0
    __shared__ float h_s[8][2][NH];       // per-warp h for its 2 edges
    __shared__ float red_s[8 * NH];       // cross-warp reduction of agg
    __shared__ float agg_s[NH];
    __shared__ float h1_s[NH];
    __shared__ float h2_s[NH];
    __shared__ float x_s[ND];

    const int tid  = threadIdx.x;
    const int node = blockIdx.x;          // ((b*49 + t)*64 + n)
    const int n    = node & 63;
    const int bt   = node >> 6;
    const int t    = bt % TO;
    const int b    = bt / TO;

    // --- stage shared state ---
    for (int i = tid; i < NH * NH; i += 256) w2t_s[i] = g_w2t[i];
    if (tid < NH) u_s[tid] = g_u[node * NH + tid];
    if (tid < 64) {
        float r = 0.f;
        if (tid < EPN)
            r = rel_type[((size_t)b * (NN * EPN) + n * EPN + tid) * 2 + 1];
        rt_s[tid] = r;
    }
    if (tid < ND) x_s[tid] = inputs[(((size_t)b * NN + n) * NT + t) * ND + tid];
    __syncthreads();

    const int warp = tid >> 5;
    const int lane = tid & 31;
    const float* vbase = g_v + (size_t)(bt * NN) * NH;

    const float bj0 = fc2_b[NH + lane * 2];       // fc2_b[1][2*lane]
    const float bj1 = fc2_b[NH + lane * 2 + 1];

    float agg0 = 0.f, agg1 = 0.f;                 // this warp's partial agg[2l], agg[2l+1]

#pragma unroll 1
    for (int it = 0; it < 4; it++) {
        const int s0 = it * 16 + warp * 2;
        const int s1 = s0 + 1;
        // slot s maps to send node: s + (s >= n); slot 63 is dummy (rt=0)
        const int send0 = (s0 >= EPN) ? n : (s0 + (s0 >= n ? 1 : 0));
        const int send1 = (s1 >= EPN) ? n : (s1 + (s1 >= n ? 1 : 0));

        const float* v0 = vbase + send0 * NH;
        const float* v1 = vbase + send1 * NH;
        const float ua = u_s[lane];
        const float ub = u_s[lane + 32];
        h_s[warp][0][lane]      = fmaxf(ua + v0[lane],      0.f);
        h_s[warp][0][lane + 32] = fmaxf(ub + v0[lane + 32], 0.f);
        h_s[warp][1][lane]      = fmaxf(ua + v1[lane],      0.f);
        h_s[warp][1][lane + 32] = fmaxf(ub + v1[lane + 32], 0.f);
        __syncwarp();

        float a00 = 0.f, a01 = 0.f, a10 = 0.f, a11 = 0.f;
#pragma unroll
        for (int k = 0; k < NH; k++) {
            const float2 w2 = *(const float2*)&w2t_s[k * NH + lane * 2];
            const float hh0 = h_s[warp][0][k];
            const float hh1 = h_s[warp][1][k];
            a00 += w2.x * hh0;
            a01 += w2.y * hh0;
            a10 += w2.x * hh1;
            a11 += w2.y * hh1;
        }
        const float r0 = rt_s[s0];
        const float r1 = rt_s[s1];
        agg0 += fmaxf(a00 + bj0, 0.f) * r0 + fmaxf(a10 + bj0, 0.f) * r1;
        agg1 += fmaxf(a01 + bj1, 0.f) * r0 + fmaxf(a11 + bj1, 0.f) * r1;
        __syncwarp();   // all lanes done reading h_s before next iter overwrites
    }

    red_s[warp * NH + lane * 2]     = agg0;
    red_s[warp * NH + lane * 2 + 1] = agg1;
    __syncthreads();

    if (tid < NH) {
        float a = 0.f;
#pragma unroll
        for (int w = 0; w < 8; w++) a += red_s[w * NH + tid];
        agg_s[tid] = a;
    }
    __syncthreads();

    // --- node MLP: aug = [x (4), agg (64)] ---
    if (tid < NH) {
        const float* w = out1_w + tid * (ND + NH);
        float acc = out1_b[tid];
#pragma unroll
        for (int d = 0; d < ND; d++) acc += w[d] * x_s[d];
#pragma unroll
        for (int k = 0; k < NH; k++) acc += w[ND + k] * agg_s[k];
        h1_s[tid] = fmaxf(acc, 0.f);
    }
    __syncthreads();
    if (tid < NH) {
        const float* w = out2_w + tid * NH;
        float acc = out2_b[tid];
#pragma unroll
        for (int k = 0; k < NH; k++) acc += w[k] * h1_s[k];
        h2_s[tid] = fmaxf(acc, 0.f);
    }
    __syncthreads();
    if (tid < ND) {
        const float* w = out3_w + tid * NH;
        float acc = out3_b[tid];
#pragma unroll
        for (int k = 0; k < NH; k++) acc += w[k] * h2_s[k];
        // out[b,n,t,d] = x_in[b,t,n,d] + delta
        out[(((size_t)b * NN + n) * TO + t) * ND + tid] = x_s[tid] + acc;
    }
}

// ---------------------------------------------------------------------------
extern "C" void kernel_launch(void* const* d_in, const int* in_sizes, int n_in,
                              void* d_out, int out_size) {
    const float* inputs   = (const float*)d_in[0];
    const float* rel_type = (const float*)d_in[1];
    // d_in[2] rel_rec, d_in[3] rel_send: one-hot by construction; indices derived analytically
    const float* fc1_w    = (const float*)d_in[4];
    const float* fc1_b    = (const float*)d_in[5];
    const float* fc2_w    = (const float*)d_in[6];
    const float* fc2_b    = (const float*)d_in[7];
    const float* out1_w   = (const float*)d_in[8];
    const float* out1_b   = (const float*)d_in[9];
    const float* out2_w   = (const float*)d_in[10];
    const float* out2_b   = (const float*)d_in[11];
    const float* out3_w   = (const float*)d_in[12];
    const float* out3_b   = (const float*)d_in[13];
    float* out = (float*)d_out;

    k_prep<<<(NH * NH + 255) / 256, 256>>>(fc2_w);

    const int n_embed = NB * TO * NN * NH;
    k_node_embed<<<(n_embed + 255) / 256, 256>>>(inputs, fc1_w, fc1_b);

    k_edge<<<NB * TO * NN, 256>>>(inputs, rel_type, fc2_b,
                                  out1_w, out1_b, out2_w, out2_b,
                                  out3_w, out3_b, out);
}

// round 2
// speedup vs baseline: 1.2483x; 1.2483x over previous
#include <cuda_runtime.h>

#define NB 8
#define NN 64
#define NT 50
#define TO 49      // output timesteps (t = NT-1 never needed)
#define ND 4
#define NH 64
#define EPN 63     // real edges per recv node (slot 63 is a dummy, rt=0)

// Scratch (static __device__ — no allocation in kernel_launch)
__device__ float g_u[NB * TO * NN * NH];   // u' = W1r @ x + b1   (per node)
__device__ float g_v[NB * TO * NN * NH];   // v  = W1s @ x        (per node)
__device__ float g_w2t[NH * NH];           // fc2_w[1] transposed: [k][j]

// ---------------------------------------------------------------------------
// packed f32x2 helpers
__device__ __forceinline__ unsigned long long pack_dup(float x) {
    unsigned long long r;
    unsigned int u = __float_as_uint(x);
    asm("mov.b64 %0, {%1, %1};" : "=l"(r) : "r"(u));
    return r;
}
__device__ __forceinline__ void fma2(unsigned long long& d,
                                     unsigned long long a,
                                     unsigned long long b) {
    asm("fma.rn.f32x2 %0, %1, %2, %0;" : "+l"(d) : "l"(a), "l"(b));
}
__device__ __forceinline__ void unpack2(unsigned long long v, float& lo, float& hi) {
    unsigned int a, b;
    asm("mov.b64 {%0, %1}, %2;" : "=r"(a), "=r"(b) : "l"(v));
    lo = __uint_as_float(a);
    hi = __uint_as_float(b);
}

// ---------------------------------------------------------------------------
// Kernel 0: transpose fc2_w[1] into g_w2t ([k][j]) for coalesced register loads.
__global__ void k_prep(const float* __restrict__ fc2_w) {
    int idx = blockIdx.x * blockDim.x + threadIdx.x;
    if (idx >= NH * NH) return;
    int j = idx >> 6;
    int k = idx & 63;
    g_w2t[k * NH + j] = fc2_w[NH * NH + j * NH + k];   // fc2_w[1][j][k]
}

// ---------------------------------------------------------------------------
// Kernel 1: per-node fc1 factorization.
__global__ void k_node_embed(const float* __restrict__ inputs,
                             const float* __restrict__ fc1_w,
                             const float* __restrict__ fc1_b) {
    int gid = blockIdx.x * blockDim.x + threadIdx.x;
    if (gid >= NB * TO * NN * NH) return;
    int h    = gid & 63;
    int node = gid >> 6;              // ((b*49 + t)*64 + n)
    int n    = node & 63;
    int bt   = node >> 6;
    int t    = bt % TO;
    int b    = bt / TO;

    const float* x = inputs + (((size_t)b * NN + n) * NT + t) * ND;
    const float* w = fc1_w + NH * 2 * ND + h * 2 * ND;   // fc1_w[1][h][:]
    float u = fc1_b[NH + h];
    float v = 0.f;
#pragma unroll
    for (int d = 0; d < ND; d++) {
        u += w[d] * x[d];
        v += w[ND + d] * x[d];
    }
    g_u[gid] = u;
    g_v[gid] = v;
}

// ---------------------------------------------------------------------------
// Kernel 2: fused edge MLP (fc2, register-blocked f32x2) + aggregation + node MLP.
// One block per (b, t, recv n). 128 threads = 4 warps; each warp owns 16
// edge-slots (8 edge-pairs). W2 lives in registers (wA/wB, 128 regs/lane);
// h is staged in smem interleaved by edge-pair so the broadcast LDS.64 yields
// (h_e0,k , h_e1,k) directly into the f32x2 lanes.
__global__ void __launch_bounds__(128, 1)
k_edge(const float* __restrict__ inputs,
       const float* __restrict__ rel_type,
       const float* __restrict__ fc2_b,
       const float* __restrict__ out1_w, const float* __restrict__ out1_b,
       const float* __restrict__ out2_w, const float* __restrict__ out2_b,
       const float* __restrict__ out3_w, const float* __restrict__ out3_b,
       float* __restrict__ out) {
    __shared__ unsigned long long h2_s[32 * NH];  // [epair][k] -> (h_e0, h_e1)
    __shared__ float u_s[NH];
    __shared__ float rt_s[64];
    __shared__ float red_s[4 * NH];
    __shared__ float agg_s[NH];
    __shared__ float m1_s[NH];
    __shared__ float m2_s[NH];
    __shared__ float x_s[ND];

    const int tid  = threadIdx.x;
    const int node = blockIdx.x;          // ((b*49 + t)*64 + n)
    const int n    = node & 63;
    const int bt   = node >> 6;
    const int t    = bt % TO;
    const int b    = bt / TO;
    const int lane = tid & 31;
    const int warp = tid >> 5;

    if (tid < NH) u_s[tid] = g_u[(size_t)node * NH + tid];
    if (tid < 64) {
        float r = 0.f;
        if (tid < EPN)
            r = rel_type[((size_t)b * (NN * EPN) + n * EPN + tid) * 2 + 1];
        rt_s[tid] = r;
    }
    if (tid < ND) x_s[tid] = inputs[(((size_t)b * NN + n) * NT + t) * ND + tid];

    // W2 into registers: lane owns output columns (lane) and (lane+32).
    float wA[NH], wB[NH];
#pragma unroll
    for (int k = 0; k < NH; k++) {
        wA[k] = g_w2t[k * NH + lane];
        wB[k] = g_w2t[k * NH + lane + 32];
    }
    __syncthreads();

    // Stage h = relu(u[recv] + v[send]) for this warp's 16 slots, interleaved
    // by edge-pair: hf[(ep*NH + k)*2 + (s&1)].
    {
        const float* vbase = g_v + (size_t)(bt * NN) * NH;
        float* hf = (float*)h2_s;
#pragma unroll
        for (int i = 0; i < 16; i++) {
            int s = warp * 16 + i;
            int send = (s >= EPN) ? n : (s + (s >= n ? 1 : 0));
            const float* v = vbase + send * NH;
            float ha = fmaxf(u_s[lane]      + v[lane],      0.f);
            float hb = fmaxf(u_s[lane + 32] + v[lane + 32], 0.f);
            int ep = s >> 1, eo = s & 1;
            hf[(ep * NH + lane) * 2 + eo]        = ha;
            hf[(ep * NH + lane + 32) * 2 + eo]   = hb;
        }
    }
    __syncwarp();   // each warp reads only its own epairs

    // Main fc2 loop: 8 edge-pairs, packed f32x2 accumulators.
    unsigned long long accA[8], accB[8];
#pragma unroll
    for (int p = 0; p < 8; p++) { accA[p] = 0ull; accB[p] = 0ull; }

    const unsigned long long* h2w = h2_s + (size_t)warp * 8 * NH;
#pragma unroll
    for (int k = 0; k < NH; k++) {
        unsigned long long wa = pack_dup(wA[k]);
        unsigned long long wb = pack_dup(wB[k]);
#pragma unroll
        for (int p = 0; p < 8; p++) {
            unsigned long long hp = h2w[p * NH + k];   // broadcast LDS.64
            fma2(accA[p], wa, hp);
            fma2(accB[p], wb, hp);
        }
    }

    // Epilogue: bias + relu + rt weighting, accumulate over this warp's edges.
    const float bjA = fc2_b[NH + lane];
    const float bjB = fc2_b[NH + lane + 32];
    float aggA = 0.f, aggB = 0.f;
#pragma unroll
    for (int p = 0; p < 8; p++) {
        int e0 = warp * 16 + p * 2;
        float r0 = rt_s[e0], r1 = rt_s[e0 + 1];
        float a0, a1, c0, c1;
        unpack2(accA[p], a0, a1);
        unpack2(accB[p], c0, c1);
        aggA += fmaxf(a0 + bjA, 0.f) * r0 + fmaxf(a1 + bjA, 0.f) * r1;
        aggB += fmaxf(c0 + bjB, 0.f) * r0 + fmaxf(c1 + bjB, 0.f) * r1;
    }
    red_s[warp * NH + lane]      = aggA;
    red_s[warp * NH + lane + 32] = aggB;
    __syncthreads();

    if (tid < NH) {
        agg_s[tid] = red_s[tid] + red_s[NH + tid] + red_s[2 * NH + tid] + red_s[3 * NH + tid];
    }
    __syncthreads();

    // Node MLP: aug = [x (4), agg (64)]
    if (tid < NH) {
        const float* w = out1_w + tid * (ND + NH);
        float acc = out1_b[tid];
#pragma unroll
        for (int d = 0; d < ND; d++) acc += w[d] * x_s[d];
#pragma unroll
        for (int k = 0; k < NH; k++) acc += w[ND + k] * agg_s[k];
        m1_s[tid] = fmaxf(acc, 0.f);
    }
    __syncthreads();
    if (tid < NH) {
        const float* w = out2_w + tid * NH;
        float acc = out2_b[tid];
#pragma unroll
        for (int k = 0; k < NH; k++) acc += w[k] * m1_s[k];
        m2_s[tid] = fmaxf(acc, 0.f);
    }
    __syncthreads();
    if (tid < ND) {
        const float* w = out3_w + tid * NH;
        float acc = out3_b[tid];
#pragma unroll
        for (int k = 0; k < NH; k++) acc += w[k] * m2_s[k];
        out[(((size_t)b * NN + n) * TO + t) * ND + tid] = x_s[tid] + acc;
    }
}

// ---------------------------------------------------------------------------
extern "C" void kernel_launch(void* const* d_in, const int* in_sizes, int n_in,
                              void* d_out, int out_size) {
    const float* inputs   = (const float*)d_in[0];
    const float* rel_type = (const float*)d_in[1];
    // d_in[2] rel_rec, d_in[3] rel_send: one-hot by construction; indices analytic
    const float* fc1_w    = (const float*)d_in[4];
    const float* fc1_b    = (const float*)d_in[5];
    const float* fc2_w    = (const float*)d_in[6];
    const float* fc2_b    = (const float*)d_in[7];
    const float* out1_w   = (const float*)d_in[8];
    const float* out1_b   = (const float*)d_in[9];
    const float* out2_w   = (const float*)d_in[10];
    const float* out2_b   = (const float*)d_in[11];
    const float* out3_w   = (const float*)d_in[12];
    const float* out3_b   = (const float*)d_in[13];
    float* out = (float*)d_out;

    k_prep<<<(NH * NH + 255) / 256, 256>>>(fc2_w);

    const int n_embed = NB * TO * NN * NH;
    k_node_embed<<<(n_embed + 255) / 256, 256>>>(inputs, fc1_w, fc1_b);

    k_edge<<<NB * TO * NN, 128>>>(inputs, rel_type, fc2_b,
                                  out1_w, out1_b, out2_w, out2_b,
                                  out3_w, out3_b, out);
}